// round 13
// baseline (speedup 1.0000x reference)
#include <cuda_runtime.h>
#include <cuda_fp16.h>
#include <math.h>
#include <cstdint>

// Problem constants
#define BB 32
#define TT 512
#define DD 512
#define EE 8
#define HH 2048

// ---------------------------------------------------------------------------
// Device-global scratch (allocation-free)
// ---------------------------------------------------------------------------
__device__ int   g_expert[BB];
__device__ int   g_pool_done;                            // zero-init, reset each run
__device__ float g_pool_part[BB][8][DD];
__device__ __half g_x16[(size_t)BB * TT * DD];          // x as fp16
__device__ __half g_w1t[(size_t)EE * HH * DD];          // W1^T : [E][H][D] fp16
__device__ __half g_w2t[(size_t)EE * DD * HH];          // W2^T : [E][D][H] fp16
__device__ __half g_h16[(size_t)BB * TT * HH];          // hidden as fp16

// ---------------------------------------------------------------------------
// Baseline-PTX helpers (sm_80-level features only; compiles at .target sm_103)
// ---------------------------------------------------------------------------
#define SWZ(bo) ((bo) ^ (((bo) >> 3) & 0x70))

#define CP_COMMIT() asm volatile("cp.async.commit_group;" ::: "memory")
#define CP_WAIT(n)  asm volatile("cp.async.wait_group %0;" :: "n"(n) : "memory")

__device__ __forceinline__ uint32_t smem_to_u32(const void* smem_ptr) {
    uint32_t addr;
    asm("{ .reg .u64 tmp; cvta.to.shared.u64 tmp, %1; cvt.u32.u64 %0, tmp; }"
        : "=r"(addr) : "l"(smem_ptr));
    return addr;
}

__device__ __forceinline__ void ldsm4(uint32_t* r, uint32_t addr) {
    asm volatile("ldmatrix.sync.aligned.m8n8.x4.shared.b16 {%0,%1,%2,%3}, [%4];"
                 : "=r"(r[0]), "=r"(r[1]), "=r"(r[2]), "=r"(r[3]) : "r"(addr));
}

__device__ __forceinline__ void mma16816(float* c, const uint32_t* a, const uint32_t* b) {
    asm volatile(
        "mma.sync.aligned.m16n8k16.row.col.f32.f16.f16.f32 "
        "{%0,%1,%2,%3}, {%4,%5,%6,%7}, {%8,%9}, {%0,%1,%2,%3};"
        : "+f"(c[0]), "+f"(c[1]), "+f"(c[2]), "+f"(c[3])
        : "r"(a[0]), "r"(a[1]), "r"(a[2]), "r"(a[3]), "r"(b[0]), "r"(b[1]));
}

// cp.async one ROWSx64(fp16) tile (128B rows, SW128-swizzled). 256 threads.
template<int ROWS>
__device__ __forceinline__ void cpa_tile(uint32_t smem_tile,
                                         const __half* __restrict__ src,
                                         int row0, int k0, int ld, int tid) {
    const char* gbase = (const char*)(src + (size_t)row0 * ld + k0);
    const size_t rs = (size_t)ld * 2;
    #pragma unroll
    for (int j = 0; j < ROWS / 32; ++j) {
        const int linear = j * 256 + tid;      // ROWS*8 chunks of 16B
        const int row = linear >> 3;
        const int c16 = linear & 7;
        const uint32_t bo = (uint32_t)(row * 128 + c16 * 16);
        const uint32_t dst = smem_tile + SWZ(bo);
        const void* g = gbase + (size_t)row * rs + (size_t)c16 * 16;
        asm volatile("cp.async.cg.shared.global [%0], [%1], 16;"
                     :: "r"(dst), "l"(g) : "memory");
    }
}

// ---------------------------------------------------------------------------
// 64(k) x 32(n) transpose+convert tile: W fp32 [K][N] -> Wt fp16 [N][K].
// 256 threads. tile must be a [64][33] float region (8.4KB).
// ---------------------------------------------------------------------------
__device__ __forceinline__ void transpose_tile64(const float* __restrict__ We,
                                                 __half* __restrict__ The,
                                                 int K, int N, int k0, int n0,
                                                 float (*tile)[33], int tid) {
    const int tx = tid & 31, ty = tid >> 5;
    #pragma unroll
    for (int i = 0; i < 8; ++i) {
        const int kk = ty + i * 8;
        tile[kk][tx] = We[(size_t)(k0 + kk) * N + n0 + tx];
    }
    __syncthreads();
    #pragma unroll
    for (int i = 0; i < 4; ++i) {
        const int nn = i * 8 + ty;
        const int n = n0 + nn;
        __half2 v = __floats2half2_rn(tile[tx * 2][nn], tile[tx * 2 + 1][nn]);
        *(__half2*)(The + (size_t)n * K + k0 + tx * 2) = v;
    }
}

// ---------------------------------------------------------------------------
// Fused preprocessing + router (one launch):
//   blocks [0, 256)        : partial mean-pool + x -> fp16 (signal g_pool_done)
//   blocks [256, 256+4096) : W1 transpose tiles (K=512 -> [H][D])
//   block  4352 (last)     : router — spins for pool, softmax+argmax, reset
// 256 threads per block. W2 transpose is folded into GEMM1 (see below).
// ---------------------------------------------------------------------------
#define PRE_POOL_BLOCKS 256
#define PRE_W1_BLOCKS   4096
#define PRE_TOTAL_BLOCKS (PRE_POOL_BLOCKS + PRE_W1_BLOCKS + 1)

__global__ void preproc_kernel(const float* __restrict__ x,
                               const float* __restrict__ W1,
                               const float* __restrict__ Wp,
                               const float* __restrict__ bp,
                               float* __restrict__ probs_out,
                               float* __restrict__ expert_out) {
    __shared__ float tile[64][33];
    const int bid = blockIdx.x;
    const int tid = threadIdx.x;

    if (bid < PRE_POOL_BLOCKS) {
        // ---- pool + x->fp16 ----
        const int b = bid >> 3, ch = bid & 7;
        const float2* xb = (const float2*)(x + (size_t)b * TT * DD);
        __half2* xo = (__half2*)(g_x16 + (size_t)b * TT * DD);
        float2 s = make_float2(0.f, 0.f);
        const int t0 = ch * 64;
        #pragma unroll 4
        for (int t = t0; t < t0 + 64; ++t) {
            float2 v = xb[(size_t)t * 256 + tid];
            s.x += v.x; s.y += v.y;
            xo[(size_t)t * 256 + tid] = __floats2half2_rn(v.x, v.y);
        }
        g_pool_part[b][ch][tid * 2]     = s.x;
        g_pool_part[b][ch][tid * 2 + 1] = s.y;
        __syncthreads();
        __threadfence();
        if (tid == 0) atomicAdd(&g_pool_done, 1);
    } else if (bid < PRE_POOL_BLOCKS + PRE_W1_BLOCKS) {
        // ---- W1 [K=512][N=2048] -> g_w1t [2048][512] ----
        const int t = bid - PRE_POOL_BLOCKS;
        const int e = t >> 9;
        const int r = t & 511;
        const int k0 = (r >> 6) * 64;
        const int n0 = (r & 63) * 32;
        transpose_tile64(W1 + (size_t)e * DD * HH,
                         g_w1t + (size_t)e * HH * DD, DD, HH, k0, n0, tile, tid);
    } else {
        // ---- router (spin for pool partials, then softmax+argmax) ----
        if (tid == 0) {
            while (atomicCAS(&g_pool_done, PRE_POOL_BLOCKS, PRE_POOL_BLOCKS)
                   != PRE_POOL_BLOCKS) { }
        }
        __syncthreads();
        __threadfence();

        __shared__ float pooled[DD];
        __shared__ float logits[EE];

        for (int d = tid; d < DD; d += 256) {
            float s = 0.f;
            #pragma unroll
            for (int ch = 0; ch < 8; ++ch) s += g_pool_part[0][0][0 * 0];  // placeholder avoided
            s = 0.f;
            #pragma unroll
            for (int ch = 0; ch < 8; ++ch) s += g_pool_part[blockIdx.y][ch][d];
            pooled[d] = s;
        }
        // NOTE: blockIdx.y is always 0 here (1D grid); the router handles all B
        // utterances itself below, so redo properly per-b:
        __syncthreads();

        for (int b = 0; b < BB; ++b) {
            for (int d = tid; d < DD; d += 256) {
                float s = 0.f;
                #pragma unroll
                for (int ch = 0; ch < 8; ++ch) s += g_pool_part[b][ch][d];
                pooled[d] = s * (1.0f / (float)TT);
            }
            __syncthreads();

            const int w = tid >> 5, lane = tid & 31;
            if (w < EE) {
                float acc = 0.f;
                for (int d = lane; d < DD; d += 32) acc += pooled[d] * Wp[d * EE + w];
                #pragma unroll
                for (int o = 16; o > 0; o >>= 1)
                    acc += __shfl_down_sync(0xffffffffu, acc, o);
                if (lane == 0) logits[w] = acc + bp[w];
            }
            __syncthreads();

            if (tid == 0) {
                float m = logits[0]; int arg = 0;
                #pragma unroll
                for (int e = 1; e < EE; ++e) if (logits[e] > m) { m = logits[e]; arg = e; }
                float ex[EE], sum = 0.f;
                #pragma unroll
                for (int e = 0; e < EE; ++e) { ex[e] = expf(logits[e] - m); sum += ex[e]; }
                const float inv = 1.0f / sum;
                #pragma unroll
                for (int e = 0; e < EE; ++e) probs_out[b * EE + e] = ex[e] * inv;
                expert_out[b] = (float)arg;
                g_expert[b]   = arg;
            }
            __syncthreads();
        }
        if (tid == 0) g_pool_done = 0;   // reset for next graph replay
    }
}

// ---------------------------------------------------------------------------
// fp16 GEMM on mma.sync.m16n8k16 (mma.sync HW ceiling ~60% tensor: at roofline):
//   C[128,128] = A[128,K] @ B[128,K]^T   (B stored [N][K] K-major)
// PHASE 1: A=x16(K=512),  B=W1t, epi: bias+relu -> fp16 -> g_h16,
//          then each CTA transposes 2 W2 tiles (hidden behind tensor work).
// PHASE 2: A=h16(K=2048), B=W2t, epi: bias -> f32 out
// 256 threads = 8 warps (2 M x 4 N), warp tile 64x32, 2 CTAs/SM.
// SMEM/stage: A 16KB + B 16KB = 32KB; 3-stage ring = 96KB.
// ---------------------------------------------------------------------------
#define STAGE_BYTES 32768
#define A_OFF  0
#define B_OFF  16384
#define GEMM_SMEM_BYTES (3 * STAGE_BYTES)

template<int PHASE>
__global__ void __launch_bounds__(256, 2)
ffn_gemm_mma(const float* __restrict__ bias_all, float* __restrict__ outf,
             const float* __restrict__ W2src)
{
    constexpr int KTOT = (PHASE == 1) ? DD : HH;       // 512 / 2048
    constexpr int NTOT = (PHASE == 1) ? HH : DD;       // 2048 / 512
    constexpr int NCH  = KTOT / 64;                    // 8 / 32

    extern __shared__ char smem[];
    const uint32_t smem_u32 = smem_to_u32(smem);
    const int tid  = threadIdx.x;
    const int wid  = tid >> 5;
    const int lane = tid & 31;

    const int b  = blockIdx.z;
    const int e  = g_expert[b];
    const int m0 = blockIdx.y * 128;
    const int n0 = blockIdx.x * 128;

    const __half *A16, *Bp;
    if (PHASE == 1) {
        A16 = g_x16 + (size_t)b * TT * DD;
        Bp  = g_w1t + (size_t)e * HH * DD;
    } else {
        A16 = g_h16 + (size_t)b * TT * HH;
        Bp  = g_w2t + (size_t)e * DD * HH;
    }
    const float* bias = bias_all + (size_t)e * NTOT;

    const int wm0 = (wid & 1) * 64;       // warp M origin (2 tiles of 64)
    const int wn0 = (wid >> 1) * 32;      // warp N origin (4 tiles of 32)

    // ldmatrix per-lane address components (SW128 swizzle folded in)
    const int aRow = wm0 + (lane & 15);
    const uint32_t aOff  = (uint32_t)aRow * 128u;
    const uint32_t aSw   = ((uint32_t)aRow & 7u) << 4;
    const uint32_t aHalf = ((uint32_t)(lane >> 4)) * 16u;

    const int bRow = wn0 + ((lane >> 4) * 8) + (lane & 7);
    const uint32_t bOff  = (uint32_t)bRow * 128u;
    const uint32_t bSw   = ((uint32_t)bRow & 7u) << 4;
    const uint32_t bHalf = ((uint32_t)((lane >> 3) & 1)) * 16u;

    float acc[4][4][4];
    #pragma unroll
    for (int mi = 0; mi < 4; ++mi)
        #pragma unroll
        for (int ni = 0; ni < 4; ++ni)
            #pragma unroll
            for (int r = 0; r < 4; ++r) acc[mi][ni][r] = 0.f;

    // Prologue: chunks 0,1 -> slots 0,1
    cpa_tile<128>(smem_u32 + 0 * STAGE_BYTES + A_OFF, A16, m0, 0, KTOT, tid);
    cpa_tile<128>(smem_u32 + 0 * STAGE_BYTES + B_OFF, Bp,  n0, 0, KTOT, tid);
    CP_COMMIT();
    cpa_tile<128>(smem_u32 + 1 * STAGE_BYTES + A_OFF, A16, m0, 64, KTOT, tid);
    cpa_tile<128>(smem_u32 + 1 * STAGE_BYTES + B_OFF, Bp,  n0, 64, KTOT, tid);
    CP_COMMIT();

    int slot = 0;
    #pragma unroll 2
    for (int c = 0; c < NCH; ++c) {
        if (c + 1 < NCH) { CP_WAIT(1); } else { CP_WAIT(0); }
        __syncthreads();

        if (c + 2 < NCH) {
            const int ps = (slot + 2 >= 3) ? slot - 1 : slot + 2;  // (c+2)%3
            const uint32_t st = smem_u32 + ps * STAGE_BYTES;
            const int k0 = (c + 2) * 64;
            cpa_tile<128>(st + A_OFF, A16, m0, k0, KTOT, tid);
            cpa_tile<128>(st + B_OFF, Bp,  n0, k0, KTOT, tid);
            CP_COMMIT();
        }

        const uint32_t stage = smem_u32 + slot * STAGE_BYTES;
        const uint32_t tA = stage + A_OFF;
        const uint32_t tB = stage + B_OFF;

        #pragma unroll
        for (int ks = 0; ks < 4; ++ks) {
            const uint32_t colA = ((uint32_t)(ks * 32) + aHalf) ^ aSw;
            const uint32_t colB = ((uint32_t)(ks * 32) + bHalf) ^ bSw;

            uint32_t a[4][4];
            #pragma unroll
            for (int mi = 0; mi < 4; ++mi)
                ldsm4(a[mi], tA + aOff + colA + mi * 2048);

            uint32_t bfrag[4][2];
            #pragma unroll
            for (int j = 0; j < 2; ++j) {
                uint32_t r[4];
                ldsm4(r, tB + bOff + colB + j * 2048);
                bfrag[2 * j][0] = r[0]; bfrag[2 * j][1] = r[1];
                bfrag[2 * j + 1][0] = r[2]; bfrag[2 * j + 1][1] = r[3];
            }

            #pragma unroll
            for (int mi = 0; mi < 4; ++mi)
                #pragma unroll
                for (int ni = 0; ni < 4; ++ni)
                    mma16816(acc[mi][ni], a[mi], bfrag[ni]);
        }

        slot = (slot + 1 >= 3) ? 0 : slot + 1;
    }

    // Epilogue. c-frag: c0 (r, col), c1 (r, col+1), c2 (r+8, col), c3 (r+8, col+1)
    const int grow0 = m0 + wm0 + (lane >> 2);
    const int gcol0 = n0 + wn0 + (lane & 3) * 2;

    #pragma unroll
    for (int mi = 0; mi < 4; ++mi) {
        #pragma unroll
        for (int ni = 0; ni < 4; ++ni) {
            const int col = gcol0 + ni * 8;
            const float2 bv = *(const float2*)(bias + col);
            const int r0 = grow0 + mi * 16;
            const int r1 = r0 + 8;

            if (PHASE == 1) {
                float v0 = fmaxf(acc[mi][ni][0] + bv.x, 0.f);
                float v1 = fmaxf(acc[mi][ni][1] + bv.y, 0.f);
                float v2 = fmaxf(acc[mi][ni][2] + bv.x, 0.f);
                float v3 = fmaxf(acc[mi][ni][3] + bv.y, 0.f);
                const size_t base0 = ((size_t)b * TT + r0) * HH + col;
                const size_t base1 = ((size_t)b * TT + r1) * HH + col;
                *(__half2*)(g_h16 + base0) = __floats2half2_rn(v0, v1);
                *(__half2*)(g_h16 + base1) = __floats2half2_rn(v2, v3);
            } else {
                float2 o0, o1;
                o0.x = acc[mi][ni][0] + bv.x; o0.y = acc[mi][ni][1] + bv.y;
                o1.x = acc[mi][ni][2] + bv.x; o1.y = acc[mi][ni][3] + bv.y;
                float* op0 = outf + ((size_t)b * TT + r0) * DD + col;
                float* op1 = outf + ((size_t)b * TT + r1) * DD + col;
                *(float2*)op0 = o0;
                *(float2*)op1 = o1;
            }
        }
    }

    // PHASE 1 tail: each CTA transposes 2 W2 tiles (overlaps other CTAs' GEMM).
    // smem slot-0 region is reused; after the final top-barrier no warp reads
    // slot 0 (last chunk lives in slot (NCH-1)%3 == 1), so writes are safe.
    if (PHASE == 1) {
        float (*tile)[33] = (float(*)[33])smem;
        const int cta = blockIdx.x + 16 * (blockIdx.y + 4 * blockIdx.z);
        #pragma unroll
        for (int i = 0; i < 2; ++i) {
            __syncthreads();
            const int t = cta * 2 + i;
            const int eW = t >> 9;
            const int r = t & 511;
            const int k0 = (r >> 4) * 64;     // K=2048: 32 k-tiles
            const int n0w = (r & 15) * 32;    // N=512 : 16 n-tiles
            transpose_tile64(W2src + (size_t)eW * HH * DD,
                             g_w2t + (size_t)eW * DD * HH, HH, DD, k0, n0w,
                             tile, tid);
        }
    }
}

// ---------------------------------------------------------------------------
// Launch. Output layout (float32): final [B*T*D] | probs [B*E] | expert [B]
// ---------------------------------------------------------------------------
extern "C" void kernel_launch(void* const* d_in, const int* in_sizes, int n_in,
                              void* d_out, int out_size)
{
    const float* x  = (const float*)d_in[0];
    const float* Wp = (const float*)d_in[1];
    const float* bp = (const float*)d_in[2];
    const float* W1 = (const float*)d_in[3];
    const float* b1 = (const float*)d_in[4];
    const float* W2 = (const float*)d_in[5];
    const float* b2 = (const float*)d_in[6];

    float* out        = (float*)d_out;
    float* final_out  = out;
    float* probs_out  = out + (size_t)BB * TT * DD;
    float* expert_out = probs_out + (size_t)BB * EE;

    cudaFuncSetAttribute(ffn_gemm_mma<1>, cudaFuncAttributeMaxDynamicSharedMemorySize,
                         GEMM_SMEM_BYTES);
    cudaFuncSetAttribute(ffn_gemm_mma<2>, cudaFuncAttributeMaxDynamicSharedMemorySize,
                         GEMM_SMEM_BYTES);

    // Fused preprocessing: pool + x->fp16 + W1 transpose + router (one launch)
    preproc_kernel<<<PRE_TOTAL_BLOCKS, 256>>>(x, W1, Wp, bp, probs_out, expert_out);

    // GEMM1: h = relu(x @ W1[e] + b1[e])   M=512, N=2048, K=512
    //        (+ W2 transpose folded into CTA tails)
    dim3 g1(HH / 128, TT / 128, BB);      // (16, 4, 32) = 2048 CTAs
    ffn_gemm_mma<1><<<g1, 256, GEMM_SMEM_BYTES>>>(b1, nullptr, W2);

    // GEMM2: out = h @ W2[e] + b2[e]       M=512, N=512, K=2048
    dim3 g2(DD / 128, TT / 128, BB);      // (4, 4, 32)
    ffn_gemm_mma<2><<<g2, 256, GEMM_SMEM_BYTES>>>(b2, final_out, nullptr);
}

// round 14
// speedup vs baseline: 1.2175x; 1.2175x over previous
#include <cuda_runtime.h>
#include <cuda_fp16.h>
#include <math.h>
#include <cstdint>

// Problem constants
#define BB 32
#define TT 512
#define DD 512
#define EE 8
#define HH 2048

// ---------------------------------------------------------------------------
// Device-global scratch (allocation-free)
// ---------------------------------------------------------------------------
__device__ int   g_expert[BB];
__device__ int   g_pool_done;            // zero at start; reset by last router
__device__ int   g_router_done;          // zero at start; reset by last router
__device__ float g_pool_part[BB][8][DD];
__device__ __half g_x16[(size_t)BB * TT * DD];          // x as fp16
__device__ __half g_w1t[(size_t)EE * HH * DD];          // W1^T : [E][H][D] fp16
__device__ __half g_w2t[(size_t)EE * DD * HH];          // W2^T : [E][D][H] fp16
__device__ __half g_h16[(size_t)BB * TT * HH];          // hidden as fp16

// ---------------------------------------------------------------------------
// Baseline-PTX helpers (sm_80-level features only; compiles at .target sm_103)
// ---------------------------------------------------------------------------
#define SWZ(bo) ((bo) ^ (((bo) >> 3) & 0x70))

#define CP_COMMIT() asm volatile("cp.async.commit_group;" ::: "memory")
#define CP_WAIT(n)  asm volatile("cp.async.wait_group %0;" :: "n"(n) : "memory")

__device__ __forceinline__ uint32_t smem_to_u32(const void* smem_ptr) {
    uint32_t addr;
    asm("{ .reg .u64 tmp; cvta.to.shared.u64 tmp, %1; cvt.u32.u64 %0, tmp; }"
        : "=r"(addr) : "l"(smem_ptr));
    return addr;
}

__device__ __forceinline__ void ldsm4(uint32_t* r, uint32_t addr) {
    asm volatile("ldmatrix.sync.aligned.m8n8.x4.shared.b16 {%0,%1,%2,%3}, [%4];"
                 : "=r"(r[0]), "=r"(r[1]), "=r"(r[2]), "=r"(r[3]) : "r"(addr));
}

__device__ __forceinline__ void mma16816(float* c, const uint32_t* a, const uint32_t* b) {
    asm volatile(
        "mma.sync.aligned.m16n8k16.row.col.f32.f16.f16.f32 "
        "{%0,%1,%2,%3}, {%4,%5,%6,%7}, {%8,%9}, {%0,%1,%2,%3};"
        : "+f"(c[0]), "+f"(c[1]), "+f"(c[2]), "+f"(c[3])
        : "r"(a[0]), "r"(a[1]), "r"(a[2]), "r"(a[3]), "r"(b[0]), "r"(b[1]));
}

// cp.async one ROWSx64(fp16) tile (128B rows, SW128-swizzled). 256 threads.
template<int ROWS>
__device__ __forceinline__ void cpa_tile(uint32_t smem_tile,
                                         const __half* __restrict__ src,
                                         int row0, int k0, int ld, int tid) {
    const char* gbase = (const char*)(src + (size_t)row0 * ld + k0);
    const size_t rs = (size_t)ld * 2;
    #pragma unroll
    for (int j = 0; j < ROWS / 32; ++j) {
        const int linear = j * 256 + tid;      // ROWS*8 chunks of 16B
        const int row = linear >> 3;
        const int c16 = linear & 7;
        const uint32_t bo = (uint32_t)(row * 128 + c16 * 16);
        const uint32_t dst = smem_tile + SWZ(bo);
        const void* g = gbase + (size_t)row * rs + (size_t)c16 * 16;
        asm volatile("cp.async.cg.shared.global [%0], [%1], 16;"
                     :: "r"(dst), "l"(g) : "memory");
    }
}

// ---------------------------------------------------------------------------
// 64(k) x 32(n) transpose+convert tile: W fp32 [K][N] -> Wt fp16 [N][K].
// 256 threads. tile is a [64][33] float smem region.
// ---------------------------------------------------------------------------
__device__ __forceinline__ void transpose_tile64(const float* __restrict__ We,
                                                 __half* __restrict__ The,
                                                 int K, int N, int k0, int n0,
                                                 float (*tile)[33], int tid) {
    const int tx = tid & 31, ty = tid >> 5;
    #pragma unroll
    for (int i = 0; i < 8; ++i) {
        const int kk = ty + i * 8;
        tile[kk][tx] = We[(size_t)(k0 + kk) * N + n0 + tx];
    }
    __syncthreads();
    #pragma unroll
    for (int i = 0; i < 4; ++i) {
        const int nn = i * 8 + ty;
        const int n = n0 + nn;
        __half2 v = __floats2half2_rn(tile[tx * 2][nn], tile[tx * 2 + 1][nn]);
        *(__half2*)(The + (size_t)n * K + k0 + tx * 2) = v;
    }
}

// ---------------------------------------------------------------------------
// Fused preprocessing + router (one launch):
//   blocks [0, 256)            : partial mean-pool + x->fp16 (signal pool_done)
//   blocks [256, 4352)         : W1 transpose tiles
//   blocks [4352, 8448)        : W2 transpose tiles
//   blocks [8448, 8480)        : router, ONE PER UTTERANCE (parallel), spin on
//                                pool_done; last one resets both counters.
// 256 threads per block.
// ---------------------------------------------------------------------------
#define PRE_POOL_BLOCKS 256
#define PRE_W1_BLOCKS   4096
#define PRE_W2_BLOCKS   4096
#define PRE_ROUTER_BASE (PRE_POOL_BLOCKS + PRE_W1_BLOCKS + PRE_W2_BLOCKS)
#define PRE_TOTAL_BLOCKS (PRE_ROUTER_BASE + BB)

__global__ void preproc_kernel(const float* __restrict__ x,
                               const float* __restrict__ W1,
                               const float* __restrict__ W2,
                               const float* __restrict__ Wp,
                               const float* __restrict__ bp,
                               float* __restrict__ probs_out,
                               float* __restrict__ expert_out) {
    __shared__ float tile[64][33];
    const int bid = blockIdx.x;
    const int tid = threadIdx.x;

    if (bid < PRE_POOL_BLOCKS) {
        // ---- pool + x->fp16 ----
        const int b = bid >> 3, ch = bid & 7;
        const float2* xb = (const float2*)(x + (size_t)b * TT * DD);
        __half2* xo = (__half2*)(g_x16 + (size_t)b * TT * DD);
        float2 s = make_float2(0.f, 0.f);
        const int t0 = ch * 64;
        #pragma unroll 4
        for (int t = t0; t < t0 + 64; ++t) {
            float2 v = xb[(size_t)t * 256 + tid];
            s.x += v.x; s.y += v.y;
            xo[(size_t)t * 256 + tid] = __floats2half2_rn(v.x, v.y);
        }
        g_pool_part[b][ch][tid * 2]     = s.x;
        g_pool_part[b][ch][tid * 2 + 1] = s.y;
        __syncthreads();
        __threadfence();
        if (tid == 0) atomicAdd(&g_pool_done, 1);
    } else if (bid < PRE_POOL_BLOCKS + PRE_W1_BLOCKS) {
        // ---- W1 [K=512][N=2048] -> g_w1t [2048][512] ----
        const int t = bid - PRE_POOL_BLOCKS;
        const int e = t >> 9;
        const int r = t & 511;
        const int k0 = (r >> 6) * 64;
        const int n0 = (r & 63) * 32;
        transpose_tile64(W1 + (size_t)e * DD * HH,
                         g_w1t + (size_t)e * HH * DD, DD, HH, k0, n0, tile, tid);
    } else if (bid < PRE_ROUTER_BASE) {
        // ---- W2 [K=2048][N=512] -> g_w2t [512][2048] ----
        const int t = bid - PRE_POOL_BLOCKS - PRE_W1_BLOCKS;
        const int e = t >> 9;
        const int r = t & 511;
        const int k0 = (r >> 4) * 64;
        const int n0 = (r & 15) * 32;
        transpose_tile64(W2 + (size_t)e * HH * DD,
                         g_w2t + (size_t)e * DD * HH, HH, DD, k0, n0, tile, tid);
    } else {
        // ---- router: one block per utterance (parallel over B) ----
        const int b = bid - PRE_ROUTER_BASE;
        if (tid == 0) {
            while (atomicAdd(&g_pool_done, 0) < PRE_POOL_BLOCKS) { }
        }
        __syncthreads();
        __threadfence();

        __shared__ float pooled[DD];
        __shared__ float logits[EE];

        for (int d = tid; d < DD; d += 256) {
            float s = 0.f;
            #pragma unroll
            for (int ch = 0; ch < 8; ++ch) s += g_pool_part[b][ch][d];
            pooled[d] = s * (1.0f / (float)TT);
        }
        __syncthreads();

        const int w = tid >> 5, lane = tid & 31;
        if (w < EE) {
            float acc = 0.f;
            for (int d = lane; d < DD; d += 32) acc += pooled[d] * Wp[d * EE + w];
            #pragma unroll
            for (int o = 16; o > 0; o >>= 1)
                acc += __shfl_down_sync(0xffffffffu, acc, o);
            if (lane == 0) logits[w] = acc + bp[w];
        }
        __syncthreads();

        if (tid == 0) {
            float m = logits[0]; int arg = 0;
            #pragma unroll
            for (int e = 1; e < EE; ++e) if (logits[e] > m) { m = logits[e]; arg = e; }
            float ex[EE], sum = 0.f;
            #pragma unroll
            for (int e = 0; e < EE; ++e) { ex[e] = expf(logits[e] - m); sum += ex[e]; }
            const float inv = 1.0f / sum;
            #pragma unroll
            for (int e = 0; e < EE; ++e) probs_out[b * EE + e] = ex[e] * inv;
            expert_out[b] = (float)arg;
            g_expert[b]   = arg;

            // Last router block to finish resets both counters for the next
            // graph replay. Every router block has already passed the spin
            // gate by the time the 32nd increments, so the reset cannot hang
            // a peer.
            const int old = atomicAdd(&g_router_done, 1);
            if (old == BB - 1) {
                __threadfence();
                g_pool_done   = 0;
                g_router_done = 0;
                __threadfence();
            }
        }
    }
}

// ---------------------------------------------------------------------------
// fp16 GEMM on mma.sync.m16n8k16 (at the ~60%-tensor mma.sync HW roofline):
//   C[128,128] = A[128,K] @ B[128,K]^T   (B stored [N][K] K-major)
// PHASE 1: A=x16(K=512),  B=W1t, epi: bias+relu -> fp16 -> g_h16
// PHASE 2: A=h16(K=2048), B=W2t, epi: bias -> f32 out
// 256 threads = 8 warps (2 M x 4 N), warp tile 64x32, 2 CTAs/SM.
// SMEM/stage: A 16KB + B 16KB = 32KB; 3-stage ring = 96KB.
// Single barrier per chunk: prefetch issued AFTER the barrier, so the slot
// being overwritten ((c+2)%3 == slot of c-1) is provably drained.
// ---------------------------------------------------------------------------
#define STAGE_BYTES 32768
#define A_OFF  0
#define B_OFF  16384
#define GEMM_SMEM_BYTES (3 * STAGE_BYTES)

template<int PHASE>
__global__ void __launch_bounds__(256, 2)
ffn_gemm_mma(const float* __restrict__ bias_all, float* __restrict__ outf)
{
    constexpr int KTOT = (PHASE == 1) ? DD : HH;       // 512 / 2048
    constexpr int NTOT = (PHASE == 1) ? HH : DD;       // 2048 / 512
    constexpr int NCH  = KTOT / 64;                    // 8 / 32

    extern __shared__ char smem[];
    const uint32_t smem_u32 = smem_to_u32(smem);
    const int tid  = threadIdx.x;
    const int wid  = tid >> 5;
    const int lane = tid & 31;

    const int b  = blockIdx.z;
    const int e  = g_expert[b];
    const int m0 = blockIdx.y * 128;
    const int n0 = blockIdx.x * 128;

    const __half *A16, *Bp;
    if (PHASE == 1) {
        A16 = g_x16 + (size_t)b * TT * DD;
        Bp  = g_w1t + (size_t)e * HH * DD;
    } else {
        A16 = g_h16 + (size_t)b * TT * HH;
        Bp  = g_w2t + (size_t)e * DD * HH;
    }
    const float* bias = bias_all + (size_t)e * NTOT;

    const int wm0 = (wid & 1) * 64;       // warp M origin (2 tiles of 64)
    const int wn0 = (wid >> 1) * 32;      // warp N origin (4 tiles of 32)

    // ldmatrix per-lane address components (SW128 swizzle folded in)
    const int aRow = wm0 + (lane & 15);
    const uint32_t aOff  = (uint32_t)aRow * 128u;
    const uint32_t aSw   = ((uint32_t)aRow & 7u) << 4;
    const uint32_t aHalf = ((uint32_t)(lane >> 4)) * 16u;

    const int bRow = wn0 + ((lane >> 4) * 8) + (lane & 7);
    const uint32_t bOff  = (uint32_t)bRow * 128u;
    const uint32_t bSw   = ((uint32_t)bRow & 7u) << 4;
    const uint32_t bHalf = ((uint32_t)((lane >> 3) & 1)) * 16u;

    float acc[4][4][4];
    #pragma unroll
    for (int mi = 0; mi < 4; ++mi)
        #pragma unroll
        for (int ni = 0; ni < 4; ++ni)
            #pragma unroll
            for (int r = 0; r < 4; ++r) acc[mi][ni][r] = 0.f;

    // Prologue: chunks 0,1 -> slots 0,1
    cpa_tile<128>(smem_u32 + 0 * STAGE_BYTES + A_OFF, A16, m0, 0, KTOT, tid);
    cpa_tile<128>(smem_u32 + 0 * STAGE_BYTES + B_OFF, Bp,  n0, 0, KTOT, tid);
    CP_COMMIT();
    cpa_tile<128>(smem_u32 + 1 * STAGE_BYTES + A_OFF, A16, m0, 64, KTOT, tid);
    cpa_tile<128>(smem_u32 + 1 * STAGE_BYTES + B_OFF, Bp,  n0, 64, KTOT, tid);
    CP_COMMIT();

    int slot = 0;
    #pragma unroll 2
    for (int c = 0; c < NCH; ++c) {
        if (c + 1 < NCH) { CP_WAIT(1); } else { CP_WAIT(0); }
        __syncthreads();

        if (c + 2 < NCH) {
            const int ps = (slot + 2 >= 3) ? slot - 1 : slot + 2;  // (c+2)%3
            const uint32_t st = smem_u32 + ps * STAGE_BYTES;
            const int k0 = (c + 2) * 64;
            cpa_tile<128>(st + A_OFF, A16, m0, k0, KTOT, tid);
            cpa_tile<128>(st + B_OFF, Bp,  n0, k0, KTOT, tid);
            CP_COMMIT();
        }

        const uint32_t stage = smem_u32 + slot * STAGE_BYTES;
        const uint32_t tA = stage + A_OFF;
        const uint32_t tB = stage + B_OFF;

        #pragma unroll
        for (int ks = 0; ks < 4; ++ks) {
            const uint32_t colA = ((uint32_t)(ks * 32) + aHalf) ^ aSw;
            const uint32_t colB = ((uint32_t)(ks * 32) + bHalf) ^ bSw;

            uint32_t a[4][4];
            #pragma unroll
            for (int mi = 0; mi < 4; ++mi)
                ldsm4(a[mi], tA + aOff + colA + mi * 2048);

            uint32_t bfrag[4][2];
            #pragma unroll
            for (int j = 0; j < 2; ++j) {
                uint32_t r[4];
                ldsm4(r, tB + bOff + colB + j * 2048);
                bfrag[2 * j][0] = r[0]; bfrag[2 * j][1] = r[1];
                bfrag[2 * j + 1][0] = r[2]; bfrag[2 * j + 1][1] = r[3];
            }

            #pragma unroll
            for (int mi = 0; mi < 4; ++mi)
                #pragma unroll
                for (int ni = 0; ni < 4; ++ni)
                    mma16816(acc[mi][ni], a[mi], bfrag[ni]);
        }

        slot = (slot + 1 >= 3) ? 0 : slot + 1;
    }

    // Epilogue. c-frag: c0 (r, col), c1 (r, col+1), c2 (r+8, col), c3 (r+8, col+1)
    const int grow0 = m0 + wm0 + (lane >> 2);
    const int gcol0 = n0 + wn0 + (lane & 3) * 2;

    #pragma unroll
    for (int mi = 0; mi < 4; ++mi) {
        #pragma unroll
        for (int ni = 0; ni < 4; ++ni) {
            const int col = gcol0 + ni * 8;
            const float2 bv = *(const float2*)(bias + col);
            const int r0 = grow0 + mi * 16;
            const int r1 = r0 + 8;

            if (PHASE == 1) {
                float v0 = fmaxf(acc[mi][ni][0] + bv.x, 0.f);
                float v1 = fmaxf(acc[mi][ni][1] + bv.y, 0.f);
                float v2 = fmaxf(acc[mi][ni][2] + bv.x, 0.f);
                float v3 = fmaxf(acc[mi][ni][3] + bv.y, 0.f);
                const size_t base0 = ((size_t)b * TT + r0) * HH + col;
                const size_t base1 = ((size_t)b * TT + r1) * HH + col;
                *(__half2*)(g_h16 + base0) = __floats2half2_rn(v0, v1);
                *(__half2*)(g_h16 + base1) = __floats2half2_rn(v2, v3);
            } else {
                float2 o0, o1;
                o0.x = acc[mi][ni][0] + bv.x; o0.y = acc[mi][ni][1] + bv.y;
                o1.x = acc[mi][ni][2] + bv.x; o1.y = acc[mi][ni][3] + bv.y;
                float* op0 = outf + ((size_t)b * TT + r0) * DD + col;
                float* op1 = outf + ((size_t)b * TT + r1) * DD + col;
                *(float2*)op0 = o0;
                *(float2*)op1 = o1;
            }
        }
    }
}

// ---------------------------------------------------------------------------
// Launch. Output layout (float32): final [B*T*D] | probs [B*E] | expert [B]
// ---------------------------------------------------------------------------
extern "C" void kernel_launch(void* const* d_in, const int* in_sizes, int n_in,
                              void* d_out, int out_size)
{
    const float* x  = (const float*)d_in[0];
    const float* Wp = (const float*)d_in[1];
    const float* bp = (const float*)d_in[2];
    const float* W1 = (const float*)d_in[3];
    const float* b1 = (const float*)d_in[4];
    const float* W2 = (const float*)d_in[5];
    const float* b2 = (const float*)d_in[6];

    float* out        = (float*)d_out;
    float* final_out  = out;
    float* probs_out  = out + (size_t)BB * TT * DD;
    float* expert_out = probs_out + (size_t)BB * EE;

    cudaFuncSetAttribute(ffn_gemm_mma<1>, cudaFuncAttributeMaxDynamicSharedMemorySize,
                         GEMM_SMEM_BYTES);
    cudaFuncSetAttribute(ffn_gemm_mma<2>, cudaFuncAttributeMaxDynamicSharedMemorySize,
                         GEMM_SMEM_BYTES);

    // Fused preprocessing: pool + x->fp16 + W1/W2 transposes + parallel router
    preproc_kernel<<<PRE_TOTAL_BLOCKS, 256>>>(x, W1, W2, Wp, bp,
                                              probs_out, expert_out);

    // GEMM1: h = relu(x @ W1[e] + b1[e])   M=512, N=2048, K=512
    dim3 g1(HH / 128, TT / 128, BB);      // (16, 4, 32)
    ffn_gemm_mma<1><<<g1, 256, GEMM_SMEM_BYTES>>>(b1, nullptr);

    // GEMM2: out = h @ W2[e] + b2[e]       M=512, N=512, K=2048
    dim3 g2(DD / 128, TT / 128, BB);      // (4, 4, 32)
    ffn_gemm_mma<2><<<g2, 256, GEMM_SMEM_BYTES>>>(b2, final_out);
}